// round 4
// baseline (speedup 1.0000x reference)
#include <cuda_runtime.h>
#include <cuda_bf16.h>
#include <cstdint>

// Problem constants
#define B_      32
#define C_      3
#define H_      257
#define W_      257
#define NW_     61                 // windows per axis
#define WSZ_    289                // 17*17
#define PLANE_  (257*257)          // 66049
#define NWIN_   (B_*C_*NW_*NW_)    // 357216 windows total
#define SW_ELEMS  ((long long)NWIN_ * WSZ_)        // 103,235,424
#define S_ELEMS   ((long long)B_ * 12 * NW_ * NW_) // 1,428,864
#define S_OFF     SW_ELEMS
#define Q_OFF     (SW_ELEMS + S_ELEMS)             // 104,664,288

#define JT_       16                // windows per block (along j)
#define NJT_      4                 // ceil(61/16)
#define TILE_COLS 77                // (JT_-1)*4 + 17
#define TILE_PAD  84                // padded row stride (bank-conflict tuned)
#define TILE_ROWS 17
#define LUT_G     72                // max float4 groups per phase

// Block = 16 adjacent windows along j (same bc, i). x tile (17 x 77) staged in
// smem once (coalesced). Per-phase uint4 LUT maps output-group index -> 4 smem
// byte offsets, eliminating per-element div/mod math. Each warp processes one
// window: LDS gathers + phased float4 streaming stores + shuffle reduction.
__global__ __launch_bounds__(512) void leafnet_fused_kernel(
    const float* __restrict__ x, float* __restrict__ out)
{
    __shared__ float tile[TILE_ROWS * TILE_PAD];
    __shared__ uint4 lutv[4 * LUT_G];

    // blockIdx.x -> (bc, i, jt)
    const int jt   = blockIdx.x & 3;
    const int rest = blockIdx.x >> 2;
    const int i    = rest % NW_;
    const int bc   = rest / NW_;                // b*3 + c
    const int j0   = jt * JT_;

    // ---- Cooperative coalesced tile load: rows [4i, 4i+17), cols [4*j0, 4*j0+77)
    {
        const float* xrow = x + (size_t)bc * PLANE_ + (size_t)(i * 4) * W_;
        const int cbase = j0 * 4;
        #pragma unroll
        for (int p = 0; p < 3; p++) {
            const int idx = threadIdx.x + p * 512;  // 1309 valid
            if (idx < TILE_ROWS * TILE_COLS) {
                const int u  = idx / TILE_COLS;
                const int c  = idx - u * TILE_COLS;
                const int gc = cbase + c;
                tile[u * TILE_PAD + c] = (gc < W_) ? __ldg(xrow + u * W_ + gc) : 0.0f;
            }
        }
    }
    // ---- LUT precompute: for phase a, group g: byte offsets of elements a+4g+{0..3}
    if (threadIdx.x < 4 * LUT_G) {
        const int a  = threadIdx.x / LUT_G;
        const int g  = threadIdx.x - a * LUT_G;
        const int e0 = a + 4 * g;
        uint32_t o[4];
        #pragma unroll
        for (int tt = 0; tt < 4; tt++) {
            const int e = min(e0 + tt, WSZ_ - 1);
            const int u = (e * 241) >> 12;          // e/17, exact for e<=288
            o[tt] = (uint32_t)(4 * e + 4 * (TILE_PAD - 17) * u);
        }
        lutv[threadIdx.x] = make_uint4(o[0], o[1], o[2], o[3]);
    }
    __syncthreads();

    const int w    = threadIdx.x >> 5;          // window slot (0..15)
    const int lane = threadIdx.x & 31;
    const int j    = j0 + w;
    if (j >= NW_) return;                        // only last jt loses warps 13..15

    const int wid = (bc * NW_ + i) * NW_ + j;
    const char* wb = (const char*)tile + w * 16; // window base (w*4 floats)
    float* swp = out + (size_t)wid * WSZ_;
    float* qp  = out + (size_t)Q_OFF + (size_t)wid * WSZ_;

    const int a         = (-wid) & 3;            // head count -> 16B aligned groups
    const int ngroups   = (WSZ_ - a) >> 2;       // 71 or 72
    const int tailstart = a + (ngroups << 2);
    const int tail      = WSZ_ - tailstart;      // 0..3
    const uint4* lut    = lutv + a * LUT_G;

    float sum = 0.0f, sumsq = 0.0f, vmin = 1e30f, vmax = -1e30f;

    auto acc = [&](float v) {
        sum   += v;
        sumsq  = fmaf(v, v, sumsq);
        vmin   = fminf(vmin, v);
        vmax   = fmaxf(vmax, v);
    };

    // head elements are always row 0 (e < a <= 3): offset = 4e
    if (lane < a) {
        const float v = *(const float*)(wb + 4 * lane);
        __stcs(swp + lane, v);
        __stcs(qp  + lane, floorf(v * 64.0f));   // digitize(linspace(0,1,65)) - 1
        acc(v);
    }

    auto doGroup = [&](int g) {
        const uint4 o = lut[g];
        const float v0 = *(const float*)(wb + o.x);
        const float v1 = *(const float*)(wb + o.y);
        const float v2 = *(const float*)(wb + o.z);
        const float v3 = *(const float*)(wb + o.w);
        acc(v0); acc(v1); acc(v2); acc(v3);
        const int e0 = a + 4 * g;
        __stcs(reinterpret_cast<float4*>(swp + e0), make_float4(v0, v1, v2, v3));
        __stcs(reinterpret_cast<float4*>(qp  + e0),
               make_float4(floorf(v0 * 64.0f), floorf(v1 * 64.0f),
                           floorf(v2 * 64.0f), floorf(v3 * 64.0f)));
    };

    doGroup(lane);                               // lane      < 71 <= ngroups
    doGroup(lane + 32);                          // lane + 32 < 64 < 71
    if (lane + 64 < ngroups) doGroup(lane + 64); // 7-8 lanes
    // tail elements are always row 16 (e >= 285): offset = 4e + (pad-17)*4*16
    if (lane < tail) {
        const int e = tailstart + lane;
        const float v = *(const float*)(wb + 4 * e + 4 * (TILE_PAD - 17) * 16);
        __stcs(swp + e, v);
        __stcs(qp  + e, floorf(v * 64.0f));
        acc(v);
    }

    // Warp reduction (butterfly)
    #pragma unroll
    for (int o = 16; o > 0; o >>= 1) {
        sum   += __shfl_xor_sync(0xFFFFFFFFu, sum,   o);
        sumsq += __shfl_xor_sync(0xFFFFFFFFu, sumsq, o);
        vmin   = fminf(vmin, __shfl_xor_sync(0xFFFFFFFFu, vmin, o));
        vmax   = fmaxf(vmax, __shfl_xor_sync(0xFFFFFFFFu, vmax, o));
    }

    if (lane == 0) {
        const float inv  = 1.0f / 289.0f;
        const float mean = sum * inv;
        const float var  = fmaxf(sumsq * inv - mean * mean, 0.0f);
        const float stdv = sqrtf(var);

        const int b = bc / 3;
        const int c = bc - b * 3;
        const int pos = i * NW_ + j;
        float* sp = out + (size_t)S_OFF + (size_t)b * 12 * (NW_ * NW_);
        // channel layout: [ (max-0.5)*4 | std*4 | (max-mean)*4 | (mean-min)*4 ] x C
        sp[(0 * 3 + c) * (NW_ * NW_) + pos] = (vmax - 0.5f) * 4.0f;
        sp[(1 * 3 + c) * (NW_ * NW_) + pos] = stdv * 4.0f;
        sp[(2 * 3 + c) * (NW_ * NW_) + pos] = (vmax - mean) * 4.0f;
        sp[(3 * 3 + c) * (NW_ * NW_) + pos] = (mean - vmin) * 4.0f;
    }
}

extern "C" void kernel_launch(void* const* d_in, const int* in_sizes, int n_in,
                              void* d_out, int out_size)
{
    const float* x = (const float*)d_in[0];   // (32,3,257,257) float32
    // d_in[1] = bins (65 floats) — uniform linspace(0,1,65); digitize-1 == floor(v*64)
    float* out = (float*)d_out;

    const int threads = 512;                   // 16 warps = 16 windows / block
    const int blocks  = (B_ * C_) * NW_ * NJT_;   // 96 * 61 * 4 = 23424
    leafnet_fused_kernel<<<blocks, threads>>>(x, out);
}

// round 5
// speedup vs baseline: 1.0561x; 1.0561x over previous
#include <cuda_runtime.h>
#include <cuda_bf16.h>
#include <cstdint>

// Problem constants
#define B_      32
#define C_      3
#define H_      257
#define W_      257
#define STRIDE_ 4
#define NW_     61                 // windows per axis
#define WSZ_    289                // 17*17
#define PLANE_  (257*257)          // 66049
#define NWIN_   (B_*C_*NW_*NW_)    // 357216 windows total
#define SW_ELEMS  ((long long)NWIN_ * WSZ_)        // 103,235,424
#define S_ELEMS   ((long long)B_ * 12 * NW_ * NW_) // 1,428,864
#define S_OFF     SW_ELEMS
#define Q_OFF     (SW_ELEMS + S_ELEMS)             // 104,664,288

#define JT_       8                 // windows per block (along j)
#define NJT_      8                 // ceil(61/8)
#define TILE_COLS 45                // (JT_-1)*4 + 17
#define TILE_PAD  48                // padded row stride in smem
#define TILE_ROWS 17

// Block = 8 adjacent windows along j (same bc, i); 17x45 x-tile staged in smem
// once (coalesced). Each warp owns one window: all 12 gather-LDS issued as one
// burst (max MLP), then stats, then 6 streaming STG.128 back-to-back.
__global__ __launch_bounds__(256) void leafnet_fused_kernel(
    const float* __restrict__ x, float* __restrict__ out)
{
    __shared__ float tile[TILE_ROWS * TILE_PAD];

    // blockIdx.x -> (bc, i, jt)
    const int jt   = blockIdx.x & 7;
    const int rest = blockIdx.x >> 3;
    const int i    = rest % NW_;
    const int bc   = rest / NW_;                // b*3 + c
    const int j0   = jt * JT_;

    // ---- Cooperative coalesced tile load: rows [4i,4i+17), cols [4j0,4j0+45)
    {
        const float* xrow = x + (size_t)bc * PLANE_ + (size_t)(i * STRIDE_) * W_;
        const int cbase = j0 * STRIDE_;
        #pragma unroll
        for (int p = 0; p < 3; p++) {
            const int idx = threadIdx.x + p * 256;   // 765 valid
            if (idx < TILE_ROWS * TILE_COLS) {
                const int u  = idx / TILE_COLS;
                const int c  = idx - u * TILE_COLS;
                const int gc = cbase + c;
                tile[u * TILE_PAD + c] = (gc < W_) ? __ldg(xrow + u * W_ + gc) : 0.0f;
            }
        }
    }
    __syncthreads();

    const int w    = threadIdx.x >> 5;           // window slot (0..7)
    const int lane = threadIdx.x & 31;
    const int j    = j0 + w;
    if (j >= NW_) return;                        // only last jt loses warps 5..7

    const int wid = (bc * NW_ + i) * NW_ + j;
    const float* wsm = tile + w * STRIDE_;       // + u*TILE_PAD + v
    float* swp = out + (size_t)wid * WSZ_;
    float* qp  = out + (size_t)Q_OFF + (size_t)wid * WSZ_;

    const int a         = (-wid) & 3;            // head count -> 16B alignment
    const int ngroups   = (WSZ_ - a) >> 2;       // 71 or 72
    const int tailstart = a + (ngroups << 2);
    const int tail      = WSZ_ - tailstart;      // 0..3
    const bool p2       = (lane + 64) < ngroups; // 7-8 lanes do a 3rd group

    float sum = 0.0f, sumsq = 0.0f, vmin = 1e30f, vmax = -1e30f;
    auto acc = [&](float v) {
        sum   += v;
        sumsq  = fmaf(v, v, sumsq);
        vmin   = fminf(vmin, v);
        vmax   = fmaxf(vmax, v);
    };

    // ---- Burst phase: all 12 gather loads issued before any consumer
    float vals[12];
    #pragma unroll
    for (int g = 0; g < 3; g++) {
        const int ebase = a + 4 * (lane + 32 * g);
        #pragma unroll
        for (int tt = 0; tt < 4; tt++) {
            int e = ebase + tt;
            e = (e <= 288) ? e : 288;            // clamp g=2 overrun (predicated later)
            const int u = (e * 241) >> 12;       // e/17, exact for 0<=e<=288
            const int v = e - u * 17;
            vals[g * 4 + tt] = wsm[u * TILE_PAD + v];
        }
    }

    // head elements (e < a <= 3): always row 0
    float hv = 0.0f;
    const bool ph = lane < a;
    if (ph) { hv = wsm[lane]; acc(hv); }
    // tail elements (e >= 285): always row 16
    float tv = 0.0f;
    const bool pt = lane < tail;
    if (pt) { tv = wsm[16 * TILE_PAD + (tailstart + lane - 272)]; acc(tv); }

    // ---- Stats
    #pragma unroll
    for (int k = 0; k < 8; k++) acc(vals[k]);
    if (p2) {
        #pragma unroll
        for (int k = 8; k < 12; k++) acc(vals[k]);
    }

    // ---- Store phase: streaming, back-to-back
    const int e0 = a + 4 * lane;
    __stcs(reinterpret_cast<float4*>(swp + e0),
           make_float4(vals[0], vals[1], vals[2], vals[3]));
    __stcs(reinterpret_cast<float4*>(swp + e0 + 128),
           make_float4(vals[4], vals[5], vals[6], vals[7]));
    __stcs(reinterpret_cast<float4*>(qp + e0),
           make_float4(floorf(vals[0] * 64.0f), floorf(vals[1] * 64.0f),
                       floorf(vals[2] * 64.0f), floorf(vals[3] * 64.0f)));
    __stcs(reinterpret_cast<float4*>(qp + e0 + 128),
           make_float4(floorf(vals[4] * 64.0f), floorf(vals[5] * 64.0f),
                       floorf(vals[6] * 64.0f), floorf(vals[7] * 64.0f)));
    if (p2) {
        __stcs(reinterpret_cast<float4*>(swp + e0 + 256),
               make_float4(vals[8], vals[9], vals[10], vals[11]));
        __stcs(reinterpret_cast<float4*>(qp + e0 + 256),
               make_float4(floorf(vals[8] * 64.0f), floorf(vals[9] * 64.0f),
                           floorf(vals[10] * 64.0f), floorf(vals[11] * 64.0f)));
    }
    if (ph) {
        __stcs(swp + lane, hv);
        __stcs(qp  + lane, floorf(hv * 64.0f));  // digitize(linspace(0,1,65)) - 1
    }
    if (pt) {
        const int e = tailstart + lane;
        __stcs(swp + e, tv);
        __stcs(qp  + e, floorf(tv * 64.0f));
    }

    // ---- Warp reduction (butterfly)
    #pragma unroll
    for (int o = 16; o > 0; o >>= 1) {
        sum   += __shfl_xor_sync(0xFFFFFFFFu, sum,   o);
        sumsq += __shfl_xor_sync(0xFFFFFFFFu, sumsq, o);
        vmin   = fminf(vmin, __shfl_xor_sync(0xFFFFFFFFu, vmin, o));
        vmax   = fmaxf(vmax, __shfl_xor_sync(0xFFFFFFFFu, vmax, o));
    }

    if (lane == 0) {
        const float inv  = 1.0f / 289.0f;
        const float mean = sum * inv;
        const float var  = fmaxf(sumsq * inv - mean * mean, 0.0f);
        const float stdv = sqrtf(var);

        const int b = bc / 3;
        const int c = bc - b * 3;
        const int pos = i * NW_ + j;
        float* sp = out + (size_t)S_OFF + (size_t)b * 12 * (NW_ * NW_);
        // channel layout: [ (max-0.5)*4 | std*4 | (max-mean)*4 | (mean-min)*4 ] x C
        sp[(0 * 3 + c) * (NW_ * NW_) + pos] = (vmax - 0.5f) * 4.0f;
        sp[(1 * 3 + c) * (NW_ * NW_) + pos] = stdv * 4.0f;
        sp[(2 * 3 + c) * (NW_ * NW_) + pos] = (vmax - mean) * 4.0f;
        sp[(3 * 3 + c) * (NW_ * NW_) + pos] = (mean - vmin) * 4.0f;
    }
}

extern "C" void kernel_launch(void* const* d_in, const int* in_sizes, int n_in,
                              void* d_out, int out_size)
{
    const float* x = (const float*)d_in[0];   // (32,3,257,257) float32
    // d_in[1] = bins (65 floats) — uniform linspace(0,1,65); digitize-1 == floor(v*64)
    float* out = (float*)d_out;

    const int threads = 256;                   // 8 warps = 8 windows / block
    const int blocks  = (B_ * C_) * NW_ * NJT_;   // 96 * 61 * 8 = 46848
    leafnet_fused_kernel<<<blocks, threads>>>(x, out);
}